// round 6
// baseline (speedup 1.0000x reference)
#include <cuda_runtime.h>
#include <math.h>

#define B_TOTAL 32768
#define NM 6
#define T 30
#define TPB 256
#define AB 256                    // agents per block (1 thread/agent)
#define NBLK (B_TOTAL / AB)       // 128 -> single wave

// shared layout (float offsets)
#define OFF_W     0               // 256 rows x 80 ([Whh row(64) | Wih row(16)]) = 20480
#define OFF_B     20480           // 256 combined bias
#define OFF_WPOS  20736           // 12x64 = 768
#define OFF_BPOS  21504           // 16 (12 used)
#define OFF_WSE   21520           // 16x12 = 192
#define OFF_BSE   21712           // 16
#define OFF_WCONF 21728           // 6x64 = 384
#define OFF_BCONF 22112           // 16 (6 used)
#define OFF_C     22128           // AB x 66 = 16896
#define OFF_HN    39024           // AB x 66 = 16896
#define SMEM_FLOATS 55920
#define SMEM_BYTES (SMEM_FLOATS * 4)   // 223680 B (same as R5 -- proven)

#define AST 66                    // per-agent stride (floats), 8B-aligned, conflict-free

#define CONF_BASE ((size_t)B_TOTAL * NM * T * 2)

typedef unsigned long long u64_t;

// packed f32x2 fma: d = a*b + d  (SASS FFMA2)
__device__ __forceinline__ void fma2(u64_t& d, u64_t a, u64_t b) {
    asm("fma.rn.f32x2 %0, %1, %2, %0;" : "+l"(d) : "l"(a), "l"(b));
}
__device__ __forceinline__ u64_t pack2(float lo, float hi) {
    u64_t r; asm("mov.b64 %0, {%1, %2};" : "=l"(r) : "f"(lo), "f"(hi)); return r;
}
__device__ __forceinline__ float hsum2(u64_t v) {
    float a, b; asm("mov.b64 {%0, %1}, %2;" : "=f"(a), "=f"(b) : "l"(v));
    return a + b;
}
__device__ __forceinline__ float frcp_(float x) {
    float r; asm("rcp.approx.f32 %0, %1;" : "=f"(r) : "f"(x)); return r;
}
__device__ __forceinline__ float tanh_(float v) {
    float r; asm("tanh.approx.f32 %0, %1;" : "=f"(r) : "f"(v)); return r;
}
__device__ __forceinline__ float fsig(float v)  { return fmaf(0.5f, tanh_(0.5f * v), 0.5f); }

__global__ void __launch_bounds__(TPB, 1)
decoder_lstm_kernel(const float* __restrict__ traj_rel,
                    const float* __restrict__ h0,
                    const float* __restrict__ c0,
                    const float* __restrict__ W_ih,
                    const float* __restrict__ W_hh,
                    const float* __restrict__ b_ih,
                    const float* __restrict__ b_hh,
                    const float* __restrict__ W_se,
                    const float* __restrict__ b_se,
                    const float* __restrict__ W_pos,
                    const float* __restrict__ b_pos,
                    const float* __restrict__ W_conf,
                    const float* __restrict__ b_conf,
                    float* __restrict__ out)
{
    extern __shared__ float sm[];
    float* sW     = sm + OFF_W;
    float* sB     = sm + OFF_B;
    float* sWpos  = sm + OFF_WPOS;
    float* sBpos  = sm + OFF_BPOS;
    float* sWse   = sm + OFF_WSE;
    float* sBse   = sm + OFF_BSE;
    float* sWconf = sm + OFF_WCONF;
    float* sBconf = sm + OFF_BCONF;
    float* sC     = sm + OFF_C;
    float* sHN    = sm + OFF_HN;

    const int tid = threadIdx.x;

    // ---- stage weights (grid-stride, TPB=256) ----
    for (int i = tid; i < 256 * 80; i += TPB) {
        int r = i / 80, c = i % 80;
        sW[i] = (c < 64) ? W_hh[r * 64 + c] : W_ih[r * 16 + (c - 64)];
    }
    if (tid < 256) sB[tid] = b_ih[tid] + b_hh[tid];
    for (int i = tid; i < 12 * 64; i += TPB) sWpos[i] = W_pos[i];
    if (tid < 12) sBpos[tid] = b_pos[tid];
    if (tid < 192) sWse[tid] = W_se[tid];
    if (tid < 16) sBse[tid] = b_se[tid];
    for (int i = tid; i < 384; i += TPB) sWconf[i] = W_conf[i];
    if (tid < 6) sBconf[tid] = b_conf[tid];

    const int agent = blockIdx.x * AB + tid;
    float* myC  = sC + tid * AST;
    float* myHN = sHN + tid * AST;

    // c0 into shared (padded row, conflict-free: bank = (tid + k) % 32)
    {
        const float4* cv = (const float4*)(c0 + (size_t)agent * 64);
        #pragma unroll
        for (int i = 0; i < 16; i++) {
            float4 v = cv[i];
            myC[4 * i + 0] = v.x; myC[4 * i + 1] = v.y;
            myC[4 * i + 2] = v.z; myC[4 * i + 3] = v.w;
        }
    }
    __syncthreads();

    // vh[0..31] = h pairs, vh[32..39] = x pairs (all registers)
    u64_t vh[40];
    {
        const u64_t* hv = (const u64_t*)(h0 + (size_t)agent * 64);
        #pragma unroll
        for (int i = 0; i < 32; i++) vh[i] = hv[i];
    }
    {   // initial x from traj_rel (rel12 = [rx,ry]*6)
        float rx = traj_rel[2 * agent], ry = traj_rel[2 * agent + 1];
        float xs[16];
        #pragma unroll
        for (int e = 0; e < 16; e++) {
            float se = 0.f, so = 0.f;
            #pragma unroll
            for (int q = 0; q < 6; q++) { se += sWse[e * 12 + 2 * q]; so += sWse[e * 12 + 2 * q + 1]; }
            float s = sBse[e] + rx * se + ry * so;
            xs[e] = s > 0.f ? s : 0.01f * s;
        }
        #pragma unroll
        for (int m = 0; m < 8; m++) vh[32 + m] = pack2(xs[2 * m], xs[2 * m + 1]);
    }

    float* outp = out + (size_t)agent * (NM * T * 2);

    for (int t = 0; t < T; t++) {
        // ---- all 64 cells of my agent; weight reads are full-warp broadcast ----
        #pragma unroll 2
        for (int k = 0; k < 64; k++) {
            const ulonglong2* w0 = (const ulonglong2*)(sW + k * 80);
            const ulonglong2* w1 = (const ulonglong2*)(sW + (64 + k) * 80);
            const ulonglong2* w2 = (const ulonglong2*)(sW + (128 + k) * 80);
            const ulonglong2* w3 = (const ulonglong2*)(sW + (192 + k) * 80);
            u64_t a0 = 0ull, a1 = 0ull, a2 = 0ull, a3 = 0ull;
            #pragma unroll
            for (int b = 0; b < 10; b++) {
                ulonglong2 p0 = w0[2 * b], r0 = w0[2 * b + 1];
                ulonglong2 p1 = w1[2 * b], r1 = w1[2 * b + 1];
                ulonglong2 p2 = w2[2 * b], r2 = w2[2 * b + 1];
                ulonglong2 p3 = w3[2 * b], r3 = w3[2 * b + 1];
                u64_t vA = vh[4 * b], vB = vh[4 * b + 1], vC = vh[4 * b + 2], vD = vh[4 * b + 3];
                fma2(a0, p0.x, vA); fma2(a0, p0.y, vB); fma2(a0, r0.x, vC); fma2(a0, r0.y, vD);
                fma2(a1, p1.x, vA); fma2(a1, p1.y, vB); fma2(a1, r1.x, vC); fma2(a1, r1.y, vD);
                fma2(a2, p2.x, vA); fma2(a2, p2.y, vB); fma2(a2, r2.x, vC); fma2(a2, r2.y, vD);
                fma2(a3, p3.x, vA); fma2(a3, p3.y, vB); fma2(a3, r3.x, vC); fma2(a3, r3.y, vD);
            }
            float gi = hsum2(a0) + sB[k];
            float gf = hsum2(a1) + sB[64 + k];
            float gg = hsum2(a2) + sB[128 + k];
            float go = hsum2(a3) + sB[192 + k];
            float cc = fsig(gf) * myC[k] + fsig(gi) * tanh_(gg);
            myC[k] = cc;
            myHN[k] = fsig(go) * tanh_(cc);
        }

        // re-pack new h (same thread wrote it; program order suffices)
        {
            const u64_t* hv = (const u64_t*)myHN;   // tid*66*4 = 264*tid, 8B-aligned
            #pragma unroll
            for (int j = 0; j < 32; j++) vh[j] = hv[j];
        }

        // ---- rel = h @ Wpos^T + bpos (all 12 per thread), write pred pairs ----
        u64_t rel2[6];
        #pragma unroll
        for (int q = 0; q < 6; q++) {
            const u64_t* wpE = (const u64_t*)(sWpos + (2 * q) * 64);
            const u64_t* wpO = (const u64_t*)(sWpos + (2 * q + 1) * 64);
            u64_t ae = 0ull, ao = 0ull;
            #pragma unroll
            for (int j = 0; j < 32; j++) { fma2(ae, wpE[j], vh[j]); fma2(ao, wpO[j], vh[j]); }
            float re = hsum2(ae) + sBpos[2 * q];
            float ro = hsum2(ao) + sBpos[2 * q + 1];
            u64_t pr = pack2(re, ro);
            rel2[q] = pr;
            *(u64_t*)(outp + q * 60 + t * 2) = pr;   // pred[agent][m=q][t][0..1], 8B-aligned
        }

        // ---- x = lrelu(rel @ Wse^T + bse) ----
        float xs[16];
        #pragma unroll
        for (int e = 0; e < 16; e++) {
            const u64_t* we = (const u64_t*)(sWse + e * 12);
            u64_t acc = 0ull;
            #pragma unroll
            for (int q = 0; q < 6; q++) fma2(acc, we[q], rel2[q]);
            float s = hsum2(acc) + sBse[e];
            xs[e] = s > 0.f ? s : 0.01f * s;
        }
        #pragma unroll
        for (int m = 0; m < 8; m++) vh[32 + m] = pack2(xs[2 * m], xs[2 * m + 1]);
    }

    // ---- confidence head: softmax(h @ Wconf^T + bconf) ----
    float l[6];
    #pragma unroll
    for (int m = 0; m < 6; m++) {
        const u64_t* wc = (const u64_t*)(sWconf + m * 64);
        u64_t acc = 0ull;
        #pragma unroll
        for (int j = 0; j < 32; j++) fma2(acc, wc[j], vh[j]);
        l[m] = hsum2(acc) + sBconf[m];
    }
    float mx = l[0];
    #pragma unroll
    for (int m = 1; m < 6; m++) mx = fmaxf(mx, l[m]);
    float den = 0.f;
    #pragma unroll
    for (int m = 0; m < 6; m++) { l[m] = __expf(l[m] - mx); den += l[m]; }
    float inv = frcp_(den);
    float* cb = out + CONF_BASE + (size_t)agent * NM;
    *(u64_t*)(cb + 0) = pack2(l[0] * inv, l[1] * inv);
    *(u64_t*)(cb + 2) = pack2(l[2] * inv, l[3] * inv);
    *(u64_t*)(cb + 4) = pack2(l[4] * inv, l[5] * inv);
}

extern "C" void kernel_launch(void* const* d_in, const int* in_sizes, int n_in,
                              void* d_out, int out_size)
{
    // 0 traj_abs (unused), 1 traj_rel, 2 h0, 3 c0, 4 W_ih, 5 W_hh,
    // 6 b_ih, 7 b_hh, 8 W_se, 9 b_se, 10 W_pos, 11 b_pos, 12 W_conf, 13 b_conf
    const float* traj_rel = (const float*)d_in[1];
    const float* h0       = (const float*)d_in[2];
    const float* c0       = (const float*)d_in[3];
    const float* W_ih     = (const float*)d_in[4];
    const float* W_hh     = (const float*)d_in[5];
    const float* b_ih     = (const float*)d_in[6];
    const float* b_hh     = (const float*)d_in[7];
    const float* W_se     = (const float*)d_in[8];
    const float* b_se     = (const float*)d_in[9];
    const float* W_pos    = (const float*)d_in[10];
    const float* b_pos    = (const float*)d_in[11];
    const float* W_conf   = (const float*)d_in[12];
    const float* b_conf   = (const float*)d_in[13];
    float* out = (float*)d_out;

    (void)cudaFuncSetAttribute(decoder_lstm_kernel,
                               cudaFuncAttributeMaxDynamicSharedMemorySize,
                               SMEM_BYTES);

    decoder_lstm_kernel<<<NBLK, TPB, SMEM_BYTES>>>(
        traj_rel, h0, c0, W_ih, W_hh, b_ih, b_hh,
        W_se, b_se, W_pos, b_pos, W_conf, b_conf, out);
}

// round 8
// speedup vs baseline: 2.9522x; 2.9522x over previous
#include <cuda_runtime.h>
#include <math.h>

#define B_TOTAL 32768
#define NM 6
#define T 30
#define TPB 512
#define AB 256                    // agents per block (2 threads/agent)
#define NBLK (B_TOTAL / AB)       // 128 -> single wave

// shared layout (float offsets)
#define OFF_W     0               // interleaved gate weights: 4*32*20*8 = 20480
#define OFF_B     20480           // 256 combined bias
#define OFF_WPOS  20736           // 12x64 = 768
#define OFF_BPOS  21504           // 16 (12 used)
#define OFF_WSE   21520           // 16x12 = 192
#define OFF_BSE   21712           // 16
#define OFF_WCONF 21728           // 6x64 = 384
#define OFF_BCONF 22112           // 16 (6 used)
#define OFF_C     22128           // AB x 66 = 16896
#define OFF_HN    39024           // AB x 66 = 16896
#define SMEM_FLOATS 55920
#define SMEM_BYTES (SMEM_FLOATS * 4)   // 223680 B

#define AST 66                    // per-agent stride (floats) for c / hn

#define CONF_BASE ((size_t)B_TOTAL * NM * T * 2)

typedef unsigned long long u64_t;

// packed f32x2 fma: d = a*b + d  (SASS FFMA2)
__device__ __forceinline__ void fma2(u64_t& d, u64_t a, u64_t b) {
    asm("fma.rn.f32x2 %0, %1, %2, %0;" : "+l"(d) : "l"(a), "l"(b));
}
__device__ __forceinline__ u64_t pack2(float lo, float hi) {
    u64_t r; asm("mov.b64 %0, {%1, %2};" : "=l"(r) : "f"(lo), "f"(hi)); return r;
}
__device__ __forceinline__ float hsum2(u64_t v) {
    float a, b; asm("mov.b64 {%0, %1}, %2;" : "=f"(a), "=f"(b) : "l"(v));
    return a + b;
}
__device__ __forceinline__ float frcp_(float x) {
    float r; asm("rcp.approx.f32 %0, %1;" : "=f"(r) : "f"(x)); return r;
}
__device__ __forceinline__ float tanh_(float v) {
    float r; asm("tanh.approx.f32 %0, %1;" : "=f"(r) : "f"(v)); return r;
}
__device__ __forceinline__ float fsig(float v)  { return fmaf(0.5f, tanh_(0.5f * v), 0.5f); }

__global__ void __launch_bounds__(TPB, 1)
decoder_lstm_kernel(const float* __restrict__ traj_rel,
                    const float* __restrict__ h0,
                    const float* __restrict__ c0,
                    const float* __restrict__ W_ih,
                    const float* __restrict__ W_hh,
                    const float* __restrict__ b_ih,
                    const float* __restrict__ b_hh,
                    const float* __restrict__ W_se,
                    const float* __restrict__ b_se,
                    const float* __restrict__ W_pos,
                    const float* __restrict__ b_pos,
                    const float* __restrict__ W_conf,
                    const float* __restrict__ b_conf,
                    float* __restrict__ out)
{
    extern __shared__ float sm[];
    float* sW     = sm + OFF_W;
    float* sB     = sm + OFF_B;
    float* sWpos  = sm + OFF_WPOS;
    float* sBpos  = sm + OFF_BPOS;
    float* sWse   = sm + OFF_WSE;
    float* sBse   = sm + OFF_BSE;
    float* sWconf = sm + OFF_WCONF;
    float* sBconf = sm + OFF_BCONF;
    float* sC     = sm + OFF_C;
    float* sHN    = sm + OFF_HN;

    const int tid = threadIdx.x;

    // ---- stage gate weights, parity-interleaved ----
    // slot = (g*32 + ip)*20 + jj, 8 floats/slot: [even-row 4 | odd-row 4]
    // source row = g*64 + 2*ip + p, col = jj*4 + c  (cols 0..63 Whh, 64..79 Wih)
    for (int i = tid; i < 256 * 80; i += TPB) {
        int slot = i >> 3, p = (i >> 2) & 1, c = i & 3;
        int jj = slot % 20, gi_ = slot / 20;
        int g = gi_ >> 5, ip = gi_ & 31;
        int row = g * 64 + 2 * ip + p;
        int col = jj * 4 + c;
        sW[i] = (col < 64) ? W_hh[row * 64 + col] : W_ih[row * 16 + (col - 64)];
    }
    if (tid < 256) sB[tid] = b_ih[tid] + b_hh[tid];
    for (int i = tid; i < 12 * 64; i += TPB) sWpos[i] = W_pos[i];
    if (tid < 12) sBpos[tid] = b_pos[tid];
    if (tid < 192) sWse[tid] = W_se[tid];
    if (tid < 16) sBse[tid] = b_se[tid];
    for (int i = tid; i < 384; i += TPB) sWconf[i] = W_conf[i];
    if (tid < 6) sBconf[tid] = b_conf[tid];

    const int al = tid >> 1;       // local agent (0..255)
    const int hf = tid & 1;        // parity half: cells k = 2i+hf
    const int agent = blockIdx.x * AB + al;

    // c0 into shared (conflict-free padded layout)
    {
        const float* cg = c0 + (size_t)agent * 64;
        #pragma unroll
        for (int i = 0; i < 32; i++) sC[al * AST + 2 * i + hf] = cg[2 * i + hf];
    }
    __syncthreads();

    // vh[0..31] = h pairs, vh[32..39] = x pairs
    u64_t vh[40];
    {
        const u64_t* hv = (const u64_t*)(h0 + (size_t)agent * 64);
        #pragma unroll
        for (int i = 0; i < 32; i++) vh[i] = hv[i];
    }
    {   // initial x from traj_rel
        float rx = traj_rel[2 * agent], ry = traj_rel[2 * agent + 1];
        float xs[16];
        #pragma unroll
        for (int e = 0; e < 16; e++) {
            float se = 0.f, so = 0.f;
            #pragma unroll
            for (int q = 0; q < 6; q++) { se += sWse[e * 12 + 2 * q]; so += sWse[e * 12 + 2 * q + 1]; }
            float s = sBse[e] + rx * se + ry * so;
            xs[e] = s > 0.f ? s : 0.01f * s;
        }
        #pragma unroll
        for (int m = 0; m < 8; m++) vh[32 + m] = pack2(xs[2 * m], xs[2 * m + 1]);
    }

    float* outp = out + (size_t)agent * (NM * T * 2);
    float* myC  = sC + al * AST;
    float* myHN = sHN + al * AST;
    const u64_t* myHN2 = (const u64_t*)(sHN + al * AST);
    const ulonglong2* wiv = ((const ulonglong2*)sW) + hf;  // parity base

    for (int t = 0; t < T; t++) {
        // ---- gates + state update for my 32 cells ----
        #pragma unroll 1
        for (int i = 0; i < 32; i++) {
            const int k = 2 * i + hf;
            // slot*2 + hf (ulonglong2 units); both parities in the same 128B line
            const ulonglong2* w0 = wiv + ((0 * 32 + i) * 20) * 2;
            const ulonglong2* w1 = wiv + ((1 * 32 + i) * 20) * 2;
            const ulonglong2* w2 = wiv + ((2 * 32 + i) * 20) * 2;
            const ulonglong2* w3 = wiv + ((3 * 32 + i) * 20) * 2;
            u64_t a0 = 0ull, a1 = 0ull, a2 = 0ull, a3 = 0ull;
            #pragma unroll
            for (int jj = 0; jj < 20; jj++) {
                ulonglong2 q0 = w0[2 * jj], q1 = w1[2 * jj], q2 = w2[2 * jj], q3 = w3[2 * jj];
                u64_t vA = vh[2 * jj], vB = vh[2 * jj + 1];
                fma2(a0, q0.x, vA); fma2(a0, q0.y, vB);
                fma2(a1, q1.x, vA); fma2(a1, q1.y, vB);
                fma2(a2, q2.x, vA); fma2(a2, q2.y, vB);
                fma2(a3, q3.x, vA); fma2(a3, q3.y, vB);
            }
            float gi = hsum2(a0) + sB[k];
            float gf = hsum2(a1) + sB[64 + k];
            float gg = hsum2(a2) + sB[128 + k];
            float go = hsum2(a3) + sB[192 + k];
            float cc = fsig(gf) * myC[k] + fsig(gi) * tanh_(gg);
            myC[k] = cc;
            myHN[k] = fsig(go) * tanh_(cc);
        }

        // partner's hn writes: warp-local visibility, reload packed
        __syncwarp();
        #pragma unroll
        for (int i = 0; i < 32; i++) vh[i] = myHN2[i];

        // ---- rel = h @ Wpos^T + bpos (6 of 12 per thread, p = 2q+hf) ----
        float rl[6];
        #pragma unroll
        for (int q = 0; q < 6; q++) {
            const int p = 2 * q + hf;
            const u64_t* wp = (const u64_t*)(sWpos + p * 64);
            u64_t acc = 0ull;
            #pragma unroll
            for (int j = 0; j < 32; j++) fma2(acc, wp[j], vh[j]);
            float r = hsum2(acc) + sBpos[p];
            rl[q] = r;
            outp[q * 60 + t * 2 + hf] = r;
        }

        // ---- pair up rel across the two lanes ----
        u64_t rel2[6];
        #pragma unroll
        for (int q = 0; q < 6; q++) {
            float oth = __shfl_xor_sync(0xffffffffu, rl[q], 1);
            rel2[q] = hf ? pack2(oth, rl[q]) : pack2(rl[q], oth);
        }

        // ---- x = lrelu(rel @ Wse^T + bse) ----
        float xs[16];
        #pragma unroll
        for (int e = 0; e < 16; e++) {
            const u64_t* we = (const u64_t*)(sWse + e * 12);
            u64_t acc = 0ull;
            #pragma unroll
            for (int q = 0; q < 6; q++) fma2(acc, we[q], rel2[q]);
            float s = hsum2(acc) + sBse[e];
            xs[e] = s > 0.f ? s : 0.01f * s;
        }
        #pragma unroll
        for (int m = 0; m < 8; m++) vh[32 + m] = pack2(xs[2 * m], xs[2 * m + 1]);
    }

    // ---- confidence head ----
    float lgo[3];
    #pragma unroll
    for (int q = 0; q < 3; q++) {
        const int m = 2 * q + hf;
        const u64_t* wc = (const u64_t*)(sWconf + m * 64);
        u64_t acc = 0ull;
        #pragma unroll
        for (int j = 0; j < 32; j++) fma2(acc, wc[j], vh[j]);
        lgo[q] = hsum2(acc) + sBconf[m];
    }
    float l[6];
    #pragma unroll
    for (int q = 0; q < 3; q++) {
        float oth = __shfl_xor_sync(0xffffffffu, lgo[q], 1);
        l[2 * q + hf] = lgo[q];
        l[2 * q + (hf ^ 1)] = oth;
    }
    float mx = l[0];
    #pragma unroll
    for (int m = 1; m < 6; m++) mx = fmaxf(mx, l[m]);
    float den = 0.f;
    #pragma unroll
    for (int m = 0; m < 6; m++) { l[m] = __expf(l[m] - mx); den += l[m]; }
    float inv = frcp_(den);
    #pragma unroll
    for (int q = 0; q < 3; q++)
        out[CONF_BASE + (size_t)agent * NM + 2 * q + hf] = l[2 * q + hf] * inv;
}

extern "C" void kernel_launch(void* const* d_in, const int* in_sizes, int n_in,
                              void* d_out, int out_size)
{
    // 0 traj_abs (unused), 1 traj_rel, 2 h0, 3 c0, 4 W_ih, 5 W_hh,
    // 6 b_ih, 7 b_hh, 8 W_se, 9 b_se, 10 W_pos, 11 b_pos, 12 W_conf, 13 b_conf
    const float* traj_rel = (const float*)d_in[1];
    const float* h0       = (const float*)d_in[2];
    const float* c0       = (const float*)d_in[3];
    const float* W_ih     = (const float*)d_in[4];
    const float* W_hh     = (const float*)d_in[5];
    const float* b_ih     = (const float*)d_in[6];
    const float* b_hh     = (const float*)d_in[7];
    const float* W_se     = (const float*)d_in[8];
    const float* b_se     = (const float*)d_in[9];
    const float* W_pos    = (const float*)d_in[10];
    const float* b_pos    = (const float*)d_in[11];
    const float* W_conf   = (const float*)d_in[12];
    const float* b_conf   = (const float*)d_in[13];
    float* out = (float*)d_out;

    (void)cudaFuncSetAttribute(decoder_lstm_kernel,
                               cudaFuncAttributeMaxDynamicSharedMemorySize,
                               SMEM_BYTES);

    decoder_lstm_kernel<<<NBLK, TPB, SMEM_BYTES>>>(
        traj_rel, h0, c0, W_ih, W_hh, b_ih, b_hh,
        W_se, b_se, W_pos, b_pos, W_conf, b_conf, out);
}

// round 11
// speedup vs baseline: 6.3333x; 2.1453x over previous
#include <cuda_runtime.h>
#include <math.h>

#define B_TOTAL 32768
#define NM 6
#define T 30
#define TPB 256
#define WARPS 8
#define AB 128                     // agents per block (16 per warp)
#define NBLK (B_TOTAL / AB)        // 256

// smem float offsets
#define OFF_BH 0                   // gate W hi frags: 10*32*64 = 20480
#define OFF_BL 20480               // gate W lo frags: 20480
#define OFF_PH 40960               // Wpos hi: 8*2*64 = 1024
#define OFF_PL 41984
#define OFF_SH 43008               // Wse hi: 2*2*64 = 256
#define OFF_SL 43264
#define OFF_CH 43520               // Wconf hi: 8*1*64 = 512
#define OFF_CL 44032
#define OFF_BG 44544               // 256
#define OFF_BP 44800               // 16
#define OFF_BS 44816               // 16
#define OFF_BC 44832               // 8
#define OFF_HX 44840               // 8 warps * 16 rows * 84
#define HXW 84
#define SMEM_FLOATS (OFF_HX + WARPS * 16 * HXW)   // 55592
#define SMEM_BYTES (SMEM_FLOATS * 4)              // 222368

#define CONF_BASE ((size_t)B_TOTAL * NM * T * 2)

__device__ __forceinline__ unsigned tf32h(float f) {
    unsigned u; asm("cvt.rna.tf32.f32 %0, %1;" : "=r"(u) : "f"(f)); return u;
}
__device__ __forceinline__ void tf32pair(float f, unsigned& hi, unsigned& lo) {
    hi = tf32h(f);
    lo = tf32h(f - __uint_as_float(hi));
}
__device__ __forceinline__ void mma8(float* d, const unsigned* a, unsigned b0, unsigned b1) {
    asm("mma.sync.aligned.m16n8k8.row.col.f32.tf32.tf32.f32 "
        "{%0,%1,%2,%3},{%4,%5,%6,%7},{%8,%9},{%0,%1,%2,%3};"
        : "+f"(d[0]), "+f"(d[1]), "+f"(d[2]), "+f"(d[3])
        : "r"(a[0]), "r"(a[1]), "r"(a[2]), "r"(a[3]), "r"(b0), "r"(b1));
}
__device__ __forceinline__ float frcp_(float x) {
    float r; asm("rcp.approx.f32 %0, %1;" : "=f"(r) : "f"(x)); return r;
}
__device__ __forceinline__ float tanh_(float v) {
    float r; asm("tanh.approx.f32 %0, %1;" : "=f"(r) : "f"(v)); return r;
}
__device__ __forceinline__ float fsig(float v) { return fmaf(0.5f, tanh_(0.5f * v), 0.5f); }

// load A fragment (m16k8, row-major) for this warp tile from fp32 scratch, as tf32 hi/lo
__device__ __forceinline__ void load_afrag(const float* rowg, const float* rowg8, int q,
                                           int basecol, unsigned* H, unsigned* L) {
    tf32pair(rowg [basecol + q],     H[0], L[0]);   // a0: (g,   c)
    tf32pair(rowg8[basecol + q],     H[1], L[1]);   // a1: (g+8, c)
    tf32pair(rowg [basecol + q + 4], H[2], L[2]);   // a2: (g,   c+4)
    tf32pair(rowg8[basecol + q + 4], H[3], L[3]);   // a3: (g+8, c+4)
}

__global__ void __launch_bounds__(TPB, 1)
decoder_lstm_kernel(const float* __restrict__ traj_rel,
                    const float* __restrict__ h0,
                    const float* __restrict__ c0,
                    const float* __restrict__ W_ih,
                    const float* __restrict__ W_hh,
                    const float* __restrict__ b_ih,
                    const float* __restrict__ b_hh,
                    const float* __restrict__ W_se,
                    const float* __restrict__ b_se,
                    const float* __restrict__ W_pos,
                    const float* __restrict__ b_pos,
                    const float* __restrict__ W_conf,
                    const float* __restrict__ b_conf,
                    float* __restrict__ out)
{
    extern __shared__ float sm[];
    const int tid = threadIdx.x;

    // ---- stage gate weights as frag-major tf32 hi/lo ----
    // frag element: lane (g,q), reg r -> B(k = ch*8 + q + 4r, n = nt*8 + g)
    for (int idx = tid; idx < 20480; idx += TPB) {
        int ch = idx / 2048, rem = idx - ch * 2048;
        int nt = rem >> 6, pos = rem & 63;
        int lane = pos >> 1, r = pos & 1;
        int gg = lane >> 2, qq = lane & 3;
        int n = nt * 8 + gg;                  // gate unit row (0..255)
        int k = ch * 8 + qq + 4 * r;          // 0..79
        float v = (k < 64) ? W_hh[n * 64 + k] : W_ih[n * 16 + (k - 64)];
        unsigned hi = tf32h(v);
        sm[OFF_BH + idx] = __uint_as_float(hi);
        sm[OFF_BL + idx] = __uint_as_float(tf32h(v - __uint_as_float(hi)));
    }
    for (int idx = tid; idx < 1024; idx += TPB) {
        int ch = idx >> 7, nt = (idx >> 6) & 1, pos = idx & 63;
        int lane = pos >> 1, r = pos & 1, gg = lane >> 2, qq = lane & 3;
        int p = nt * 8 + gg;
        int k = ch * 8 + qq + 4 * r;
        float v = (p < 12) ? W_pos[p * 64 + k] : 0.f;
        unsigned hi = tf32h(v);
        sm[OFF_PH + idx] = __uint_as_float(hi);
        sm[OFF_PL + idx] = __uint_as_float(tf32h(v - __uint_as_float(hi)));
    }
    for (int idx = tid; idx < 256; idx += TPB) {
        int ch = idx >> 7, nt = (idx >> 6) & 1, pos = idx & 63;
        int lane = pos >> 1, r = pos & 1, gg = lane >> 2, qq = lane & 3;
        int e = nt * 8 + gg;
        int p = ch * 8 + qq + 4 * r;
        float v = (p < 12) ? W_se[e * 12 + p] : 0.f;
        unsigned hi = tf32h(v);
        sm[OFF_SH + idx] = __uint_as_float(hi);
        sm[OFF_SL + idx] = __uint_as_float(tf32h(v - __uint_as_float(hi)));
    }
    for (int idx = tid; idx < 512; idx += TPB) {
        int ch = idx >> 6, pos = idx & 63;
        int lane = pos >> 1, r = pos & 1, gg = lane >> 2, qq = lane & 3;
        int m = gg;
        int k = ch * 8 + qq + 4 * r;
        float v = (m < 6) ? W_conf[m * 64 + k] : 0.f;
        unsigned hi = tf32h(v);
        sm[OFF_CH + idx] = __uint_as_float(hi);
        sm[OFF_CL + idx] = __uint_as_float(tf32h(v - __uint_as_float(hi)));
    }
    if (tid < 256) sm[OFF_BG + tid] = b_ih[tid] + b_hh[tid];
    if (tid < 16)  sm[OFF_BP + tid] = (tid < 12) ? b_pos[tid] : 0.f;
    if (tid < 16)  sm[OFF_BS + tid] = b_se[tid];
    if (tid < 8)   sm[OFF_BC + tid] = (tid < 6) ? b_conf[tid] : 0.f;

    const int w = tid >> 5, l = tid & 31, g = l >> 2, q = l & 3;
    const int ag0 = blockIdx.x * AB + w * 16;
    float* hx = sm + OFF_HX + w * (16 * HXW);

    // h0 -> scratch cols 0..63 (coalesced)
    for (int i = l; i < 1024; i += 32) {
        int row = i >> 6, k = i & 63;
        hx[row * HXW + k] = h0[(size_t)(ag0 + row) * 64 + k];
    }
    // initial x -> scratch cols 64..79
    for (int i = l; i < 256; i += 32) {
        int row = i >> 4, e = i & 15;
        float rx = traj_rel[(ag0 + row) * 2], ry = traj_rel[(ag0 + row) * 2 + 1];
        float se = 0.f, so = 0.f;
        #pragma unroll
        for (int p = 0; p < 6; p++) { se += W_se[e * 12 + 2 * p]; so += W_se[e * 12 + 2 * p + 1]; }
        float s = b_se[e] + rx * se + ry * so;
        hx[row * HXW + 64 + e] = s > 0.f ? s : 0.01f * s;
    }
    __syncthreads();

    // c state in registers: c_[grp*4+j]; j: 0=(g,8g'+2q) 1=(g,+1) 2=(g+8,2q) 3=(g+8,+1)
    float c_[32];
    #pragma unroll
    for (int grp = 0; grp < 8; grp++) {
        c_[grp * 4 + 0] = c0[(size_t)(ag0 + g) * 64 + grp * 8 + 2 * q];
        c_[grp * 4 + 1] = c0[(size_t)(ag0 + g) * 64 + grp * 8 + 2 * q + 1];
        c_[grp * 4 + 2] = c0[(size_t)(ag0 + g + 8) * 64 + grp * 8 + 2 * q];
        c_[grp * 4 + 3] = c0[(size_t)(ag0 + g + 8) * 64 + grp * 8 + 2 * q + 1];
    }

    const float2* pBH = (const float2*)(sm + OFF_BH);
    const float2* pBL = (const float2*)(sm + OFF_BL);
    const float2* pPH = (const float2*)(sm + OFF_PH);
    const float2* pPL = (const float2*)(sm + OFF_PL);
    const float2* pSH = (const float2*)(sm + OFF_SH);
    const float2* pSL = (const float2*)(sm + OFF_SL);
    const float2* pCH = (const float2*)(sm + OFF_CH);
    const float2* pCL = (const float2*)(sm + OFF_CL);
    float* rowg  = hx + g * HXW;
    float* rowg8 = hx + (g + 8) * HXW;
    float* outA = out + (size_t)(ag0 + g) * 360;
    float* outB = out + (size_t)(ag0 + g + 8) * 360;

    #pragma unroll 1
    for (int t = 0; t < T; t++) {
        __syncwarp();
        // ---- A fragments (h cols 0..63, x cols 64..79), tf32 hi/lo ----
        unsigned Ah[10][4], Al[10][4];
        #pragma unroll
        for (int ch = 0; ch < 10; ch++)
            load_afrag(rowg, rowg8, q, ch * 8, Ah[ch], Al[ch]);

        // ---- gates: 8 groups of 8 cells ----
        #pragma unroll
        for (int grp = 0; grp < 8; grp++) {
            float acc[4][4];
            #pragma unroll
            for (int gate = 0; gate < 4; gate++) {
                const float* bb = sm + OFF_BG + gate * 64 + grp * 8 + 2 * q;
                acc[gate][0] = bb[0]; acc[gate][1] = bb[1];
                acc[gate][2] = bb[0]; acc[gate][3] = bb[1];
            }
            #pragma unroll
            for (int ch = 0; ch < 10; ch++) {
                #pragma unroll
                for (int gate = 0; gate < 4; gate++) {
                    int fidx = (ch * 32 + gate * 8 + grp) * 32 + l;
                    float2 bh = pBH[fidx], bl = pBL[fidx];
                    unsigned bh0 = __float_as_uint(bh.x), bh1 = __float_as_uint(bh.y);
                    mma8(acc[gate], Ah[ch], bh0, bh1);
                    mma8(acc[gate], Ah[ch], __float_as_uint(bl.x), __float_as_uint(bl.y));
                    mma8(acc[gate], Al[ch], bh0, bh1);
                }
            }
            float hv[4];
            #pragma unroll
            for (int j = 0; j < 4; j++) {
                float cc = fsig(acc[1][j]) * c_[grp * 4 + j] + fsig(acc[0][j]) * tanh_(acc[2][j]);
                c_[grp * 4 + j] = cc;
                hv[j] = fsig(acc[3][j]) * tanh_(cc);
            }
            *(float2*)(rowg  + grp * 8 + 2 * q) = make_float2(hv[0], hv[1]);
            *(float2*)(rowg8 + grp * 8 + 2 * q) = make_float2(hv[2], hv[3]);
        }
        __syncwarp();

        // ---- rel = h_new @ Wpos^T + bpos ----
        float ar[2][4];
        ar[0][0] = sm[OFF_BP + 2 * q];     ar[0][1] = sm[OFF_BP + 2 * q + 1];
        ar[0][2] = ar[0][0];               ar[0][3] = ar[0][1];
        ar[1][0] = sm[OFF_BP + 8 + 2 * q]; ar[1][1] = sm[OFF_BP + 8 + 2 * q + 1];
        ar[1][2] = ar[1][0];               ar[1][3] = ar[1][1];
        #pragma unroll
        for (int ch = 0; ch < 8; ch++) {
            unsigned rh[4], rl[4];
            load_afrag(rowg, rowg8, q, ch * 8, rh, rl);
            #pragma unroll
            for (int nt = 0; nt < 2; nt++) {
                int fidx = (ch * 2 + nt) * 32 + l;
                float2 bh = pPH[fidx], bl = pPL[fidx];
                unsigned bh0 = __float_as_uint(bh.x), bh1 = __float_as_uint(bh.y);
                mma8(ar[nt], rh, bh0, bh1);
                mma8(ar[nt], rh, __float_as_uint(bl.x), __float_as_uint(bl.y));
                mma8(ar[nt], rl, bh0, bh1);
            }
        }
        // pred writes: tile0 -> modes q, tile1 -> modes 4+q (q<2)
        *(float2*)(outA + q * 60 + t * 2) = make_float2(ar[0][0], ar[0][1]);
        *(float2*)(outB + q * 60 + t * 2) = make_float2(ar[0][2], ar[0][3]);
        if (q < 2) {
            *(float2*)(outA + (4 + q) * 60 + t * 2) = make_float2(ar[1][0], ar[1][1]);
            *(float2*)(outB + (4 + q) * 60 + t * 2) = make_float2(ar[1][2], ar[1][3]);
        }
        // rel -> scratch cols 64..75, zero-pad 76..79
        *(float2*)(rowg  + 64 + 2 * q) = make_float2(ar[0][0], ar[0][1]);
        *(float2*)(rowg8 + 64 + 2 * q) = make_float2(ar[0][2], ar[0][3]);
        {
            float2 za = (q < 2) ? make_float2(ar[1][0], ar[1][1]) : make_float2(0.f, 0.f);
            float2 zb = (q < 2) ? make_float2(ar[1][2], ar[1][3]) : make_float2(0.f, 0.f);
            *(float2*)(rowg  + 72 + 2 * q) = za;
            *(float2*)(rowg8 + 72 + 2 * q) = zb;
        }
        __syncwarp();

        // ---- x = lrelu(rel @ Wse^T + bse) ----
        float ax[2][4];
        ax[0][0] = sm[OFF_BS + 2 * q];     ax[0][1] = sm[OFF_BS + 2 * q + 1];
        ax[0][2] = ax[0][0];               ax[0][3] = ax[0][1];
        ax[1][0] = sm[OFF_BS + 8 + 2 * q]; ax[1][1] = sm[OFF_BS + 8 + 2 * q + 1];
        ax[1][2] = ax[1][0];               ax[1][3] = ax[1][1];
        #pragma unroll
        for (int ch = 0; ch < 2; ch++) {
            unsigned rh[4], rl[4];
            load_afrag(rowg, rowg8, q, 64 + ch * 8, rh, rl);
            #pragma unroll
            for (int nt = 0; nt < 2; nt++) {
                int fidx = (ch * 2 + nt) * 32 + l;
                float2 bh = pSH[fidx], bl = pSL[fidx];
                unsigned bh0 = __float_as_uint(bh.x), bh1 = __float_as_uint(bh.y);
                mma8(ax[nt], rh, bh0, bh1);
                mma8(ax[nt], rh, __float_as_uint(bl.x), __float_as_uint(bl.y));
                mma8(ax[nt], rl, bh0, bh1);
            }
        }
        #pragma unroll
        for (int nt = 0; nt < 2; nt++)
            #pragma unroll
            for (int j = 0; j < 4; j++)
                ax[nt][j] = ax[nt][j] > 0.f ? ax[nt][j] : 0.01f * ax[nt][j];
        *(float2*)(rowg  + 64 + 2 * q) = make_float2(ax[0][0], ax[0][1]);
        *(float2*)(rowg8 + 64 + 2 * q) = make_float2(ax[0][2], ax[0][3]);
        *(float2*)(rowg  + 72 + 2 * q) = make_float2(ax[1][0], ax[1][1]);
        *(float2*)(rowg8 + 72 + 2 * q) = make_float2(ax[1][2], ax[1][3]);
    }
    __syncwarp();

    // ---- confidence head: softmax(h @ Wconf^T + bconf) ----
    float ac[4];
    ac[0] = sm[OFF_BC + 2 * q]; ac[1] = sm[OFF_BC + 2 * q + 1];
    ac[2] = ac[0];              ac[3] = ac[1];
    #pragma unroll
    for (int ch = 0; ch < 8; ch++) {
        unsigned rh[4], rl[4];
        load_afrag(rowg, rowg8, q, ch * 8, rh, rl);
        int fidx = ch * 32 + l;
        float2 bh = pCH[fidx], bl = pCL[fidx];
        unsigned bh0 = __float_as_uint(bh.x), bh1 = __float_as_uint(bh.y);
        mma8(ac, rh, bh0, bh1);
        mma8(ac, rh, __float_as_uint(bl.x), __float_as_uint(bl.y));
        mma8(ac, rl, bh0, bh1);
    }
    {
        bool v0 = (2 * q) < 6, v1 = (2 * q + 1) < 6;
        float la = fmaxf(v0 ? ac[0] : -1e30f, v1 ? ac[1] : -1e30f);
        float lb = fmaxf(v0 ? ac[2] : -1e30f, v1 ? ac[3] : -1e30f);
        la = fmaxf(la, __shfl_xor_sync(0xffffffffu, la, 1));
        la = fmaxf(la, __shfl_xor_sync(0xffffffffu, la, 2));
        lb = fmaxf(lb, __shfl_xor_sync(0xffffffffu, lb, 1));
        lb = fmaxf(lb, __shfl_xor_sync(0xffffffffu, lb, 2));
        float ea0 = v0 ? __expf(ac[0] - la) : 0.f, ea1 = v1 ? __expf(ac[1] - la) : 0.f;
        float eb0 = v0 ? __expf(ac[2] - lb) : 0.f, eb1 = v1 ? __expf(ac[3] - lb) : 0.f;
        float sa = ea0 + ea1, sb = eb0 + eb1;
        sa += __shfl_xor_sync(0xffffffffu, sa, 1); sa += __shfl_xor_sync(0xffffffffu, sa, 2);
        sb += __shfl_xor_sync(0xffffffffu, sb, 1); sb += __shfl_xor_sync(0xffffffffu, sb, 2);
        float ra = frcp_(sa), rb = frcp_(sb);
        if (q < 3) {
            float* cA = out + CONF_BASE + (size_t)(ag0 + g) * NM + 2 * q;
            float* cB = out + CONF_BASE + (size_t)(ag0 + g + 8) * NM + 2 * q;
            *(float2*)cA = make_float2(ea0 * ra, ea1 * ra);
            *(float2*)cB = make_float2(eb0 * rb, eb1 * rb);
        }
    }
}

extern "C" void kernel_launch(void* const* d_in, const int* in_sizes, int n_in,
                              void* d_out, int out_size)
{
    // 0 traj_abs (unused), 1 traj_rel, 2 h0, 3 c0, 4 W_ih, 5 W_hh,
    // 6 b_ih, 7 b_hh, 8 W_se, 9 b_se, 10 W_pos, 11 b_pos, 12 W_conf, 13 b_conf
    const float* traj_rel = (const float*)d_in[1];
    const float* h0       = (const float*)d_in[2];
    const float* c0       = (const float*)d_in[3];
    const float* W_ih     = (const float*)d_in[4];
    const float* W_hh     = (const float*)d_in[5];
    const float* b_ih     = (const float*)d_in[6];
    const float* b_hh     = (const float*)d_in[7];
    const float* W_se     = (const float*)d_in[8];
    const float* b_se     = (const float*)d_in[9];
    const float* W_pos    = (const float*)d_in[10];
    const float* b_pos    = (const float*)d_in[11];
    const float* W_conf   = (const float*)d_in[12];
    const float* b_conf   = (const float*)d_in[13];
    float* out = (float*)d_out;

    (void)cudaFuncSetAttribute(decoder_lstm_kernel,
                               cudaFuncAttributeMaxDynamicSharedMemorySize,
                               SMEM_BYTES);

    decoder_lstm_kernel<<<NBLK, TPB, SMEM_BYTES>>>(
        traj_rel, h0, c0, W_ih, W_hh, b_ih, b_hh,
        W_se, b_se, W_pos, b_pos, W_conf, b_conf, out);
}

// round 12
// speedup vs baseline: 12.8478x; 2.0286x over previous
#include <cuda_runtime.h>
#include <math.h>

#define B_TOTAL 32768
#define NM 6
#define T 30
#define TPB 512
#define WARPS 16
#define AB 256                     // agents per block (16 per warp)
#define NBLK (B_TOTAL / AB)        // 128 -> single wave

// smem u32 offsets
#define OFF_GBH 0                  // gate B frags hi: 160 frags * 64 u32 = 10240
#define OFF_GBL 10240
#define OFF_PBH 20480              // Wpos: 8 frags * 64 = 512
#define OFF_PBL 20992
#define OFF_SBH 21504              // Wse: 2 frags * 64 = 128
#define OFF_SBL 21632
#define OFF_CBH 21760              // Wconf: 4 frags * 64 = 256
#define OFF_CBL 22016
#define OFF_BG  22272              // 256 floats
#define OFF_BP  22528              // 16
#define OFF_BS  22544              // 16
#define OFF_BC  22560              // 8
#define OFF_HX  22568              // 16 warps * 1408 u32 (hi 704 | lo 704)
#define HXST 44                    // row stride (u32 pairs), conflict-free
#define SMEM_U32 (OFF_HX + WARPS * 1408)     // 45096
#define SMEM_BYTES (SMEM_U32 * 4)            // 180384

#define CONF_BASE ((size_t)B_TOTAL * NM * T * 2)

__device__ __forceinline__ void stage_pair(float f0, float f1, unsigned& H, unsigned& L) {
    asm("cvt.rn.bf16x2.f32 %0, %1, %2;" : "=r"(H) : "f"(f1), "f"(f0));  // low=f0, high=f1
    float r0 = f0 - __uint_as_float(H << 16);
    float r1 = f1 - __uint_as_float(H & 0xFFFF0000u);
    asm("cvt.rn.bf16x2.f32 %0, %1, %2;" : "=r"(L) : "f"(r1), "f"(r0));
}
__device__ __forceinline__ void mmab(float* d, const unsigned* a, unsigned b0, unsigned b1) {
    asm("mma.sync.aligned.m16n8k16.row.col.f32.bf16.bf16.f32 "
        "{%0,%1,%2,%3},{%4,%5,%6,%7},{%8,%9},{%0,%1,%2,%3};"
        : "+f"(d[0]), "+f"(d[1]), "+f"(d[2]), "+f"(d[3])
        : "r"(a[0]), "r"(a[1]), "r"(a[2]), "r"(a[3]), "r"(b0), "r"(b1));
}
__device__ __forceinline__ float frcp_(float x) {
    float r; asm("rcp.approx.f32 %0, %1;" : "=f"(r) : "f"(x)); return r;
}
__device__ __forceinline__ float tanh_(float v) {
    float r; asm("tanh.approx.f32 %0, %1;" : "=f"(r) : "f"(v)); return r;
}
__device__ __forceinline__ float fsig(float v) { return fmaf(0.5f, tanh_(0.5f * v), 0.5f); }

__global__ void __launch_bounds__(TPB, 1)
decoder_lstm_kernel(const float* __restrict__ traj_rel,
                    const float* __restrict__ h0,
                    const float* __restrict__ c0,
                    const float* __restrict__ W_ih,
                    const float* __restrict__ W_hh,
                    const float* __restrict__ b_ih,
                    const float* __restrict__ b_hh,
                    const float* __restrict__ W_se,
                    const float* __restrict__ b_se,
                    const float* __restrict__ W_pos,
                    const float* __restrict__ b_pos,
                    const float* __restrict__ W_conf,
                    const float* __restrict__ b_conf,
                    float* __restrict__ out)
{
    extern __shared__ float smf[];
    unsigned* smu = (unsigned*)smf;
    const int tid = threadIdx.x;

    // ---- stage gate weights as frag-major bf16 hi/lo ----
    // frag = ch*32 + ntile (ntile = gate*8+grp); lane(g,q), reg r:
    //   n = ntile*8 + g ; k = ch*16 + r*8 + 2q (+1 for upper half)
    for (int idx = tid; idx < 10240; idx += TPB) {
        int frag = idx >> 6, rem = idx & 63, lane = rem >> 1, r = rem & 1;
        int ch = frag >> 5, ntile = frag & 31;
        int g = lane >> 2, q = lane & 3;
        int n = ntile * 8 + g;
        int k = ch * 16 + r * 8 + 2 * q;
        float v0 = (k < 64) ? W_hh[n * 64 + k] : W_ih[n * 16 + (k - 64)];
        float v1 = (k + 1 < 64) ? W_hh[n * 64 + k + 1] : W_ih[n * 16 + (k + 1 - 64)];
        unsigned H, L; stage_pair(v0, v1, H, L);
        smu[OFF_GBH + frag * 64 + lane * 2 + r] = H;
        smu[OFF_GBL + frag * 64 + lane * 2 + r] = L;
    }
    // Wpos: frags = ch*2 + nt (ch 0..3, K=64), p = nt*8+g (valid<12)
    for (int idx = tid; idx < 512; idx += TPB) {
        int frag = idx >> 6, rem = idx & 63, lane = rem >> 1, r = rem & 1;
        int ch = frag >> 1, nt = frag & 1;
        int g = lane >> 2, q = lane & 3;
        int p = nt * 8 + g;
        int k = ch * 16 + r * 8 + 2 * q;
        float v0 = (p < 12) ? W_pos[p * 64 + k] : 0.f;
        float v1 = (p < 12) ? W_pos[p * 64 + k + 1] : 0.f;
        unsigned H, L; stage_pair(v0, v1, H, L);
        smu[OFF_PBH + frag * 64 + lane * 2 + r] = H;
        smu[OFF_PBL + frag * 64 + lane * 2 + r] = L;
    }
    // Wse: frags = nt (2), K=16 (12 valid), e = nt*8+g
    for (int idx = tid; idx < 128; idx += TPB) {
        int frag = idx >> 6, rem = idx & 63, lane = rem >> 1, r = rem & 1;
        int g = lane >> 2, q = lane & 3;
        int e = frag * 8 + g;
        int k = r * 8 + 2 * q;
        float v0 = (k < 12) ? W_se[e * 12 + k] : 0.f;
        float v1 = (k + 1 < 12) ? W_se[e * 12 + k + 1] : 0.f;
        unsigned H, L; stage_pair(v0, v1, H, L);
        smu[OFF_SBH + frag * 64 + lane * 2 + r] = H;
        smu[OFF_SBL + frag * 64 + lane * 2 + r] = L;
    }
    // Wconf: frags = ch (4), m = g (valid<6)
    for (int idx = tid; idx < 256; idx += TPB) {
        int frag = idx >> 6, rem = idx & 63, lane = rem >> 1, r = rem & 1;
        int g = lane >> 2, q = lane & 3;
        int k = frag * 16 + r * 8 + 2 * q;
        float v0 = (g < 6) ? W_conf[g * 64 + k] : 0.f;
        float v1 = (g < 6) ? W_conf[g * 64 + k + 1] : 0.f;
        unsigned H, L; stage_pair(v0, v1, H, L);
        smu[OFF_CBH + frag * 64 + lane * 2 + r] = H;
        smu[OFF_CBL + frag * 64 + lane * 2 + r] = L;
    }
    if (tid < 256) smf[OFF_BG + tid] = b_ih[tid] + b_hh[tid];
    if (tid < 16)  smf[OFF_BP + tid] = (tid < 12) ? b_pos[tid] : 0.f;
    if (tid < 16)  smf[OFF_BS + tid] = b_se[tid];
    if (tid < 8)   smf[OFF_BC + tid] = (tid < 6) ? b_conf[tid] : 0.f;

    const int w = tid >> 5, l = tid & 31, g = l >> 2, q = l & 3;
    const int ag0 = blockIdx.x * AB + w * 16;
    unsigned* hxH = smu + OFF_HX + w * 1408;
    unsigned* hxL = hxH + 704;

    // ---- initial scratch: h0 (pairs 0..31) + x init (pairs 32..39), split hi/lo ----
    for (int i = l; i < 16 * 40; i += 32) {
        int row = i / 40, pr = i % 40;
        float f0, f1;
        if (pr < 32) {
            const float* hp = h0 + (size_t)(ag0 + row) * 64 + 2 * pr;
            f0 = hp[0]; f1 = hp[1];
        } else {
            float rx = traj_rel[(ag0 + row) * 2], ry = traj_rel[(ag0 + row) * 2 + 1];
            int e0 = 2 * (pr - 32);
            float xv[2];
            #pragma unroll
            for (int u = 0; u < 2; u++) {
                int e = e0 + u;
                float se = 0.f, so = 0.f;
                #pragma unroll
                for (int p = 0; p < 6; p++) { se += W_se[e * 12 + 2 * p]; so += W_se[e * 12 + 2 * p + 1]; }
                float s = b_se[e] + rx * se + ry * so;
                xv[u] = s > 0.f ? s : 0.01f * s;
            }
            f0 = xv[0]; f1 = xv[1];
        }
        unsigned H, L; stage_pair(f0, f1, H, L);
        hxH[row * HXST + pr] = H;
        hxL[row * HXST + pr] = L;
    }
    __syncthreads();

    // ---- c state in registers (D-layout mapping) ----
    float c_[32];
    #pragma unroll
    for (int grp = 0; grp < 8; grp++) {
        c_[grp * 4 + 0] = c0[(size_t)(ag0 + g) * 64 + grp * 8 + 2 * q];
        c_[grp * 4 + 1] = c0[(size_t)(ag0 + g) * 64 + grp * 8 + 2 * q + 1];
        c_[grp * 4 + 2] = c0[(size_t)(ag0 + g + 8) * 64 + grp * 8 + 2 * q];
        c_[grp * 4 + 3] = c0[(size_t)(ag0 + g + 8) * 64 + grp * 8 + 2 * q + 1];
    }

    const uint2* gBH = (const uint2*)(smu + OFF_GBH);
    const uint2* gBL = (const uint2*)(smu + OFF_GBL);
    const uint2* pBH = (const uint2*)(smu + OFF_PBH);
    const uint2* pBL = (const uint2*)(smu + OFF_PBL);
    const uint2* sBH = (const uint2*)(smu + OFF_SBH);
    const uint2* sBL = (const uint2*)(smu + OFF_SBL);
    const uint2* cBH = (const uint2*)(smu + OFF_CBH);
    const uint2* cBL = (const uint2*)(smu + OFF_CBL);
    unsigned* rHg  = hxH + g * HXST;
    unsigned* rHg8 = hxH + (g + 8) * HXST;
    unsigned* rLg  = hxL + g * HXST;
    unsigned* rLg8 = hxL + (g + 8) * HXST;
    float* outA = out + (size_t)(ag0 + g) * 360;
    float* outB = out + (size_t)(ag0 + g + 8) * 360;

    #pragma unroll 1
    for (int t = 0; t < T; t++) {
        __syncwarp();
        // ---- A fragments (5 chunks of k16 over 80 cols = 40 pairs) ----
        unsigned Ah[5][4], Al[5][4];
        #pragma unroll
        for (int ch = 0; ch < 5; ch++) {
            int b0 = ch * 8 + q;
            Ah[ch][0] = rHg[b0];  Ah[ch][1] = rHg8[b0];
            Ah[ch][2] = rHg[b0 + 4]; Ah[ch][3] = rHg8[b0 + 4];
            Al[ch][0] = rLg[b0];  Al[ch][1] = rLg8[b0];
            Al[ch][2] = rLg[b0 + 4]; Al[ch][3] = rLg8[b0 + 4];
        }

        // ---- gates: 8 groups of 8 cells ----
        #pragma unroll
        for (int grp = 0; grp < 8; grp++) {
            float acc[4][4];
            #pragma unroll
            for (int gate = 0; gate < 4; gate++) {
                const float* bb = smf + OFF_BG + gate * 64 + grp * 8 + 2 * q;
                acc[gate][0] = bb[0]; acc[gate][1] = bb[1];
                acc[gate][2] = bb[0]; acc[gate][3] = bb[1];
            }
            #pragma unroll
            for (int ch = 0; ch < 5; ch++) {
                #pragma unroll
                for (int gate = 0; gate < 4; gate++) {
                    int fi = (ch * 32 + gate * 8 + grp) * 32 + l;
                    uint2 BH = gBH[fi], BL = gBL[fi];
                    mmab(acc[gate], Ah[ch], BH.x, BH.y);
                    mmab(acc[gate], Al[ch], BH.x, BH.y);
                    mmab(acc[gate], Ah[ch], BL.x, BL.y);
                }
            }
            float hv[4];
            #pragma unroll
            for (int j = 0; j < 4; j++) {
                float cc = fsig(acc[1][j]) * c_[grp * 4 + j] + fsig(acc[0][j]) * tanh_(acc[2][j]);
                c_[grp * 4 + j] = cc;
                hv[j] = fsig(acc[3][j]) * tanh_(cc);
            }
            unsigned H, L;
            stage_pair(hv[0], hv[1], H, L);
            rHg[grp * 4 + q] = H;  rLg[grp * 4 + q] = L;
            stage_pair(hv[2], hv[3], H, L);
            rHg8[grp * 4 + q] = H; rLg8[grp * 4 + q] = L;
        }
        __syncwarp();

        // ---- rel = h_new @ Wpos^T + bpos (4 chunks) ----
        float ar[2][4];
        ar[0][0] = smf[OFF_BP + 2 * q];     ar[0][1] = smf[OFF_BP + 2 * q + 1];
        ar[0][2] = ar[0][0];                ar[0][3] = ar[0][1];
        ar[1][0] = smf[OFF_BP + 8 + 2 * q]; ar[1][1] = smf[OFF_BP + 8 + 2 * q + 1];
        ar[1][2] = ar[1][0];                ar[1][3] = ar[1][1];
        #pragma unroll
        for (int ch = 0; ch < 4; ch++) {
            int b0 = ch * 8 + q;
            unsigned rh[4] = { rHg[b0], rHg8[b0], rHg[b0 + 4], rHg8[b0 + 4] };
            unsigned rl[4] = { rLg[b0], rLg8[b0], rLg[b0 + 4], rLg8[b0 + 4] };
            #pragma unroll
            for (int nt = 0; nt < 2; nt++) {
                int fi = (ch * 2 + nt) * 32 + l;
                uint2 BH = pBH[fi], BL = pBL[fi];
                mmab(ar[nt], rh, BH.x, BH.y);
                mmab(ar[nt], rl, BH.x, BH.y);
                mmab(ar[nt], rh, BL.x, BL.y);
            }
        }
        // pred writes: mode = nt*4+q (nt=1 valid only q<2)
        *(float2*)(outA + q * 60 + t * 2) = make_float2(ar[0][0], ar[0][1]);
        *(float2*)(outB + q * 60 + t * 2) = make_float2(ar[0][2], ar[0][3]);
        if (q < 2) {
            *(float2*)(outA + (4 + q) * 60 + t * 2) = make_float2(ar[1][0], ar[1][1]);
            *(float2*)(outB + (4 + q) * 60 + t * 2) = make_float2(ar[1][2], ar[1][3]);
        }
        // rel -> scratch pairs 32..39 (cols 12..15 zeroed)
        {
            unsigned H, L;
            stage_pair(ar[0][0], ar[0][1], H, L);
            rHg[32 + q] = H;  rLg[32 + q] = L;
            stage_pair(ar[0][2], ar[0][3], H, L);
            rHg8[32 + q] = H; rLg8[32 + q] = L;
            float z0 = (q < 2) ? ar[1][0] : 0.f, z1 = (q < 2) ? ar[1][1] : 0.f;
            float z2 = (q < 2) ? ar[1][2] : 0.f, z3 = (q < 2) ? ar[1][3] : 0.f;
            stage_pair(z0, z1, H, L);
            rHg[36 + q] = H;  rLg[36 + q] = L;
            stage_pair(z2, z3, H, L);
            rHg8[36 + q] = H; rLg8[36 + q] = L;
        }
        __syncwarp();

        // ---- x = lrelu(rel @ Wse^T + bse) (1 chunk from pairs 32..39) ----
        float ax[2][4];
        ax[0][0] = smf[OFF_BS + 2 * q];     ax[0][1] = smf[OFF_BS + 2 * q + 1];
        ax[0][2] = ax[0][0];                ax[0][3] = ax[0][1];
        ax[1][0] = smf[OFF_BS + 8 + 2 * q]; ax[1][1] = smf[OFF_BS + 8 + 2 * q + 1];
        ax[1][2] = ax[1][0];                ax[1][3] = ax[1][1];
        {
            unsigned rh[4] = { rHg[32 + q], rHg8[32 + q], rHg[36 + q], rHg8[36 + q] };
            unsigned rl[4] = { rLg[32 + q], rLg8[32 + q], rLg[36 + q], rLg8[36 + q] };
            #pragma unroll
            for (int nt = 0; nt < 2; nt++) {
                int fi = nt * 32 + l;
                uint2 BH = sBH[fi], BL = sBL[fi];
                mmab(ax[nt], rh, BH.x, BH.y);
                mmab(ax[nt], rl, BH.x, BH.y);
                mmab(ax[nt], rh, BL.x, BL.y);
            }
        }
        #pragma unroll
        for (int nt = 0; nt < 2; nt++)
            #pragma unroll
            for (int j = 0; j < 4; j++)
                ax[nt][j] = ax[nt][j] > 0.f ? ax[nt][j] : 0.01f * ax[nt][j];
        {
            unsigned H, L;
            stage_pair(ax[0][0], ax[0][1], H, L); rHg[32 + q] = H;  rLg[32 + q] = L;
            stage_pair(ax[0][2], ax[0][3], H, L); rHg8[32 + q] = H; rLg8[32 + q] = L;
            stage_pair(ax[1][0], ax[1][1], H, L); rHg[36 + q] = H;  rLg[36 + q] = L;
            stage_pair(ax[1][2], ax[1][3], H, L); rHg8[36 + q] = H; rLg8[36 + q] = L;
        }
    }
    __syncwarp();

    // ---- confidence head: softmax(h @ Wconf^T + bconf) ----
    float ac[4];
    ac[0] = smf[OFF_BC + 2 * q]; ac[1] = smf[OFF_BC + 2 * q + 1];
    ac[2] = ac[0];               ac[3] = ac[1];
    #pragma unroll
    for (int ch = 0; ch < 4; ch++) {
        int b0 = ch * 8 + q;
        unsigned rh[4] = { rHg[b0], rHg8[b0], rHg[b0 + 4], rHg8[b0 + 4] };
        unsigned rl[4] = { rLg[b0], rLg8[b0], rLg[b0 + 4], rLg8[b0 + 4] };
        int fi = ch * 32 + l;
        uint2 BH = cBH[fi], BL = cBL[fi];
        mmab(ac, rh, BH.x, BH.y);
        mmab(ac, rl, BH.x, BH.y);
        mmab(ac, rh, BL.x, BL.y);
    }
    {
        bool v0 = (2 * q) < 6, v1 = (2 * q + 1) < 6;
        float la = fmaxf(v0 ? ac[0] : -1e30f, v1 ? ac[1] : -1e30f);
        float lb = fmaxf(v0 ? ac[2] : -1e30f, v1 ? ac[3] : -1e30f);
        la = fmaxf(la, __shfl_xor_sync(0xffffffffu, la, 1));
        la = fmaxf(la, __shfl_xor_sync(0xffffffffu, la, 2));
        lb = fmaxf(lb, __shfl_xor_sync(0xffffffffu, lb, 1));
        lb = fmaxf(lb, __shfl_xor_sync(0xffffffffu, lb, 2));
        float ea0 = v0 ? __expf(ac[0] - la) : 0.f, ea1 = v1 ? __expf(ac[1] - la) : 0.f;
        float eb0 = v0 ? __expf(ac[2] - lb) : 0.f, eb1 = v1 ? __expf(ac[3] - lb) : 0.f;
        float sa = ea0 + ea1, sb = eb0 + eb1;
        sa += __shfl_xor_sync(0xffffffffu, sa, 1); sa += __shfl_xor_sync(0xffffffffu, sa, 2);
        sb += __shfl_xor_sync(0xffffffffu, sb, 1); sb += __shfl_xor_sync(0xffffffffu, sb, 2);
        float ra = frcp_(sa), rb = frcp_(sb);
        if (q < 3) {
            float* cA = out + CONF_BASE + (size_t)(ag0 + g) * NM + 2 * q;
            float* cB = out + CONF_BASE + (size_t)(ag0 + g + 8) * NM + 2 * q;
            *(float2*)cA = make_float2(ea0 * ra, ea1 * ra);
            *(float2*)cB = make_float2(eb0 * rb, eb1 * rb);
        }
    }
}

extern "C" void kernel_launch(void* const* d_in, const int* in_sizes, int n_in,
                              void* d_out, int out_size)
{
    // 0 traj_abs (unused), 1 traj_rel, 2 h0, 3 c0, 4 W_ih, 5 W_hh,
    // 6 b_ih, 7 b_hh, 8 W_se, 9 b_se, 10 W_pos, 11 b_pos, 12 W_conf, 13 b_conf
    const float* traj_rel = (const float*)d_in[1];
    const float* h0       = (const float*)d_in[2];
    const float* c0       = (const float*)d_in[3];
    const float* W_ih     = (const float*)d_in[4];
    const float* W_hh     = (const float*)d_in[5];
    const float* b_ih     = (const float*)d_in[6];
    const float* b_hh     = (const float*)d_in[7];
    const float* W_se     = (const float*)d_in[8];
    const float* b_se     = (const float*)d_in[9];
    const float* W_pos    = (const float*)d_in[10];
    const float* b_pos    = (const float*)d_in[11];
    const float* W_conf   = (const float*)d_in[12];
    const float* b_conf   = (const float*)d_in[13];
    float* out = (float*)d_out;

    (void)cudaFuncSetAttribute(decoder_lstm_kernel,
                               cudaFuncAttributeMaxDynamicSharedMemorySize,
                               SMEM_BYTES);

    decoder_lstm_kernel<<<NBLK, TPB, SMEM_BYTES>>>(
        traj_rel, h0, c0, W_ih, W_hh, b_ih, b_hh,
        W_se, b_se, W_pos, b_pos, W_conf, b_conf, out);
}

// round 13
// speedup vs baseline: 12.8667x; 1.0015x over previous
#include <cuda_runtime.h>
#include <math.h>

#define B_TOTAL 32768
#define NM 6
#define T 30
#define TPB 512
#define WARPS 16
#define AB 256                     // agents per block (16 per warp)
#define NBLK (B_TOTAL / AB)        // 128 -> single wave

// smem u32 offsets
#define OFF_GBH 0                  // gate B frags hi: 160 frags * 64 u32 = 10240
#define OFF_GBL 10240
#define OFF_PBH 20480              // Wpos: 8 frags * 64 = 512
#define OFF_PBL 20992
#define OFF_SBH 21504              // Wse: 2 frags * 64 = 128
#define OFF_SBL 21632
#define OFF_CBH 21760              // Wconf: 4 frags * 64 = 256
#define OFF_CBL 22016
#define OFF_BG  22272              // 256 floats
#define OFF_BP  22528              // 16
#define OFF_BS  22544              // 16
#define OFF_BC  22560              // 8
#define OFF_HX  22568              // 16 warps * 1408 u32 (hi 704 | lo 704)
#define HXST 44                    // row stride (u32 pairs), conflict-free
#define SMEM_U32 (OFF_HX + WARPS * 1408)     // 45096
#define SMEM_BYTES (SMEM_U32 * 4)            // 180384

#define CONF_BASE ((size_t)B_TOTAL * NM * T * 2)

__device__ __forceinline__ void stage_pair(float f0, float f1, unsigned& H, unsigned& L) {
    asm("cvt.rn.bf16x2.f32 %0, %1, %2;" : "=r"(H) : "f"(f1), "f"(f0));  // low=f0, high=f1
    float r0 = f0 - __uint_as_float(H << 16);
    float r1 = f1 - __uint_as_float(H & 0xFFFF0000u);
    asm("cvt.rn.bf16x2.f32 %0, %1, %2;" : "=r"(L) : "f"(r1), "f"(r0));
}
__device__ __forceinline__ void mmab(float* d, const unsigned* a, unsigned b0, unsigned b1) {
    asm("mma.sync.aligned.m16n8k16.row.col.f32.bf16.bf16.f32 "
        "{%0,%1,%2,%3},{%4,%5,%6,%7},{%8,%9},{%0,%1,%2,%3};"
        : "+f"(d[0]), "+f"(d[1]), "+f"(d[2]), "+f"(d[3])
        : "r"(a[0]), "r"(a[1]), "r"(a[2]), "r"(a[3]), "r"(b0), "r"(b1));
}
__device__ __forceinline__ float frcp_(float x) {
    float r; asm("rcp.approx.f32 %0, %1;" : "=f"(r) : "f"(x)); return r;
}
__device__ __forceinline__ float tanh_(float v) {
    float r; asm("tanh.approx.f32 %0, %1;" : "=f"(r) : "f"(v)); return r;
}
__device__ __forceinline__ float fsig(float v) { return fmaf(0.5f, tanh_(0.5f * v), 0.5f); }

__global__ void __launch_bounds__(TPB, 1)
decoder_lstm_kernel(const float* __restrict__ traj_rel,
                    const float* __restrict__ h0,
                    const float* __restrict__ c0,
                    const float* __restrict__ W_ih,
                    const float* __restrict__ W_hh,
                    const float* __restrict__ b_ih,
                    const float* __restrict__ b_hh,
                    const float* __restrict__ W_se,
                    const float* __restrict__ b_se,
                    const float* __restrict__ W_pos,
                    const float* __restrict__ b_pos,
                    const float* __restrict__ W_conf,
                    const float* __restrict__ b_conf,
                    float* __restrict__ out)
{
    extern __shared__ float smf[];
    unsigned* smu = (unsigned*)smf;
    const int tid = threadIdx.x;

    // ---- stage gate weights as frag-major bf16 hi/lo ----
    // frag = ch*32 + ntile (ntile = gate*8+grp); lane(g,q), reg r:
    //   n = ntile*8 + g ; k = ch*16 + r*8 + 2q (+1 for upper half)
    for (int idx = tid; idx < 10240; idx += TPB) {
        int frag = idx >> 6, rem = idx & 63, lane = rem >> 1, r = rem & 1;
        int ch = frag >> 5, ntile = frag & 31;
        int g = lane >> 2, q = lane & 3;
        int n = ntile * 8 + g;
        int k = ch * 16 + r * 8 + 2 * q;
        float v0 = (k < 64) ? W_hh[n * 64 + k] : W_ih[n * 16 + (k - 64)];
        float v1 = (k + 1 < 64) ? W_hh[n * 64 + k + 1] : W_ih[n * 16 + (k + 1 - 64)];
        unsigned H, L; stage_pair(v0, v1, H, L);
        smu[OFF_GBH + frag * 64 + lane * 2 + r] = H;
        smu[OFF_GBL + frag * 64 + lane * 2 + r] = L;
    }
    // Wpos: frags = ch*2 + nt (ch 0..3, K=64), p = nt*8+g (valid<12)
    for (int idx = tid; idx < 512; idx += TPB) {
        int frag = idx >> 6, rem = idx & 63, lane = rem >> 1, r = rem & 1;
        int ch = frag >> 1, nt = frag & 1;
        int g = lane >> 2, q = lane & 3;
        int p = nt * 8 + g;
        int k = ch * 16 + r * 8 + 2 * q;
        float v0 = (p < 12) ? W_pos[p * 64 + k] : 0.f;
        float v1 = (p < 12) ? W_pos[p * 64 + k + 1] : 0.f;
        unsigned H, L; stage_pair(v0, v1, H, L);
        smu[OFF_PBH + frag * 64 + lane * 2 + r] = H;
        smu[OFF_PBL + frag * 64 + lane * 2 + r] = L;
    }
    // Wse: frags = nt (2), K=16 (12 valid), e = nt*8+g
    for (int idx = tid; idx < 128; idx += TPB) {
        int frag = idx >> 6, rem = idx & 63, lane = rem >> 1, r = rem & 1;
        int g = lane >> 2, q = lane & 3;
        int e = frag * 8 + g;
        int k = r * 8 + 2 * q;
        float v0 = (k < 12) ? W_se[e * 12 + k] : 0.f;
        float v1 = (k + 1 < 12) ? W_se[e * 12 + k + 1] : 0.f;
        unsigned H, L; stage_pair(v0, v1, H, L);
        smu[OFF_SBH + frag * 64 + lane * 2 + r] = H;
        smu[OFF_SBL + frag * 64 + lane * 2 + r] = L;
    }
    // Wconf: frags = ch (4), m = g (valid<6)
    for (int idx = tid; idx < 256; idx += TPB) {
        int frag = idx >> 6, rem = idx & 63, lane = rem >> 1, r = rem & 1;
        int g = lane >> 2, q = lane & 3;
        int k = frag * 16 + r * 8 + 2 * q;
        float v0 = (g < 6) ? W_conf[g * 64 + k] : 0.f;
        float v1 = (g < 6) ? W_conf[g * 64 + k + 1] : 0.f;
        unsigned H, L; stage_pair(v0, v1, H, L);
        smu[OFF_CBH + frag * 64 + lane * 2 + r] = H;
        smu[OFF_CBL + frag * 64 + lane * 2 + r] = L;
    }
    if (tid < 256) smf[OFF_BG + tid] = b_ih[tid] + b_hh[tid];
    if (tid < 16)  smf[OFF_BP + tid] = (tid < 12) ? b_pos[tid] : 0.f;
    if (tid < 16)  smf[OFF_BS + tid] = b_se[tid];
    if (tid < 8)   smf[OFF_BC + tid] = (tid < 6) ? b_conf[tid] : 0.f;

    const int w = tid >> 5, l = tid & 31, g = l >> 2, q = l & 3;
    const int ag0 = blockIdx.x * AB + w * 16;
    unsigned* hxH = smu + OFF_HX + w * 1408;
    unsigned* hxL = hxH + 704;

    // ---- initial scratch: h0 (pairs 0..31) + x init (pairs 32..39), split hi/lo ----
    for (int i = l; i < 16 * 40; i += 32) {
        int row = i / 40, pr = i % 40;
        float f0, f1;
        if (pr < 32) {
            const float* hp = h0 + (size_t)(ag0 + row) * 64 + 2 * pr;
            f0 = hp[0]; f1 = hp[1];
        } else {
            float rx = traj_rel[(ag0 + row) * 2], ry = traj_rel[(ag0 + row) * 2 + 1];
            int e0 = 2 * (pr - 32);
            float xv[2];
            #pragma unroll
            for (int u = 0; u < 2; u++) {
                int e = e0 + u;
                float se = 0.f, so = 0.f;
                #pragma unroll
                for (int p = 0; p < 6; p++) { se += W_se[e * 12 + 2 * p]; so += W_se[e * 12 + 2 * p + 1]; }
                float s = b_se[e] + rx * se + ry * so;
                xv[u] = s > 0.f ? s : 0.01f * s;
            }
            f0 = xv[0]; f1 = xv[1];
        }
        unsigned H, L; stage_pair(f0, f1, H, L);
        hxH[row * HXST + pr] = H;
        hxL[row * HXST + pr] = L;
    }
    __syncthreads();

    // ---- c state in registers (D-layout mapping) ----
    float c_[32];
    #pragma unroll
    for (int grp = 0; grp < 8; grp++) {
        c_[grp * 4 + 0] = c0[(size_t)(ag0 + g) * 64 + grp * 8 + 2 * q];
        c_[grp * 4 + 1] = c0[(size_t)(ag0 + g) * 64 + grp * 8 + 2 * q + 1];
        c_[grp * 4 + 2] = c0[(size_t)(ag0 + g + 8) * 64 + grp * 8 + 2 * q];
        c_[grp * 4 + 3] = c0[(size_t)(ag0 + g + 8) * 64 + grp * 8 + 2 * q + 1];
    }

    const uint2* gBH = (const uint2*)(smu + OFF_GBH);
    const uint2* gBL = (const uint2*)(smu + OFF_GBL);
    const uint2* pBH = (const uint2*)(smu + OFF_PBH);
    const uint2* pBL = (const uint2*)(smu + OFF_PBL);
    const uint2* sBH = (const uint2*)(smu + OFF_SBH);
    const uint2* sBL = (const uint2*)(smu + OFF_SBL);
    const uint2* cBH = (const uint2*)(smu + OFF_CBH);
    const uint2* cBL = (const uint2*)(smu + OFF_CBL);
    unsigned* rHg  = hxH + g * HXST;
    unsigned* rHg8 = hxH + (g + 8) * HXST;
    unsigned* rLg  = hxL + g * HXST;
    unsigned* rLg8 = hxL + (g + 8) * HXST;
    float* outA = out + (size_t)(ag0 + g) * 360;
    float* outB = out + (size_t)(ag0 + g + 8) * 360;

    #pragma unroll 1
    for (int t = 0; t < T; t++) {
        __syncwarp();
        // ---- A fragments (5 chunks of k16 over 80 cols = 40 pairs) ----
        unsigned Ah[5][4], Al[5][4];
        #pragma unroll
        for (int ch = 0; ch < 5; ch++) {
            int b0 = ch * 8 + q;
            Ah[ch][0] = rHg[b0];  Ah[ch][1] = rHg8[b0];
            Ah[ch][2] = rHg[b0 + 4]; Ah[ch][3] = rHg8[b0 + 4];
            Al[ch][0] = rLg[b0];  Al[ch][1] = rLg8[b0];
            Al[ch][2] = rLg[b0 + 4]; Al[ch][3] = rLg8[b0 + 4];
        }

        // ---- gates: 8 groups of 8 cells ----
        #pragma unroll
        for (int grp = 0; grp < 8; grp++) {
            float acc[4][4];
            #pragma unroll
            for (int gate = 0; gate < 4; gate++) {
                const float* bb = smf + OFF_BG + gate * 64 + grp * 8 + 2 * q;
                acc[gate][0] = bb[0]; acc[gate][1] = bb[1];
                acc[gate][2] = bb[0]; acc[gate][3] = bb[1];
            }
            #pragma unroll
            for (int ch = 0; ch < 5; ch++) {
                #pragma unroll
                for (int gate = 0; gate < 4; gate++) {
                    int fi = (ch * 32 + gate * 8 + grp) * 32 + l;
                    uint2 BH = gBH[fi], BL = gBL[fi];
                    mmab(acc[gate], Ah[ch], BH.x, BH.y);
                    mmab(acc[gate], Al[ch], BH.x, BH.y);
                    mmab(acc[gate], Ah[ch], BL.x, BL.y);
                }
            }
            float hv[4];
            #pragma unroll
            for (int j = 0; j < 4; j++) {
                float cc = fsig(acc[1][j]) * c_[grp * 4 + j] + fsig(acc[0][j]) * tanh_(acc[2][j]);
                c_[grp * 4 + j] = cc;
                hv[j] = fsig(acc[3][j]) * tanh_(cc);
            }
            unsigned H, L;
            stage_pair(hv[0], hv[1], H, L);
            rHg[grp * 4 + q] = H;  rLg[grp * 4 + q] = L;
            stage_pair(hv[2], hv[3], H, L);
            rHg8[grp * 4 + q] = H; rLg8[grp * 4 + q] = L;
        }
        __syncwarp();

        // ---- rel = h_new @ Wpos^T + bpos (4 chunks) ----
        float ar[2][4];
        ar[0][0] = smf[OFF_BP + 2 * q];     ar[0][1] = smf[OFF_BP + 2 * q + 1];
        ar[0][2] = ar[0][0];                ar[0][3] = ar[0][1];
        ar[1][0] = smf[OFF_BP + 8 + 2 * q]; ar[1][1] = smf[OFF_BP + 8 + 2 * q + 1];
        ar[1][2] = ar[1][0];                ar[1][3] = ar[1][1];
        #pragma unroll
        for (int ch = 0; ch < 4; ch++) {
            int b0 = ch * 8 + q;
            unsigned rh[4] = { rHg[b0], rHg8[b0], rHg[b0 + 4], rHg8[b0 + 4] };
            unsigned rl[4] = { rLg[b0], rLg8[b0], rLg[b0 + 4], rLg8[b0 + 4] };
            #pragma unroll
            for (int nt = 0; nt < 2; nt++) {
                int fi = (ch * 2 + nt) * 32 + l;
                uint2 BH = pBH[fi], BL = pBL[fi];
                mmab(ar[nt], rh, BH.x, BH.y);
                mmab(ar[nt], rl, BH.x, BH.y);
                mmab(ar[nt], rh, BL.x, BL.y);
            }
        }
        // pred writes: mode = nt*4+q (nt=1 valid only q<2)
        *(float2*)(outA + q * 60 + t * 2) = make_float2(ar[0][0], ar[0][1]);
        *(float2*)(outB + q * 60 + t * 2) = make_float2(ar[0][2], ar[0][3]);
        if (q < 2) {
            *(float2*)(outA + (4 + q) * 60 + t * 2) = make_float2(ar[1][0], ar[1][1]);
            *(float2*)(outB + (4 + q) * 60 + t * 2) = make_float2(ar[1][2], ar[1][3]);
        }
        // rel -> scratch pairs 32..39 (cols 12..15 zeroed)
        {
            unsigned H, L;
            stage_pair(ar[0][0], ar[0][1], H, L);
            rHg[32 + q] = H;  rLg[32 + q] = L;
            stage_pair(ar[0][2], ar[0][3], H, L);
            rHg8[32 + q] = H; rLg8[32 + q] = L;
            float z0 = (q < 2) ? ar[1][0] : 0.f, z1 = (q < 2) ? ar[1][1] : 0.f;
            float z2 = (q < 2) ? ar[1][2] : 0.f, z3 = (q < 2) ? ar[1][3] : 0.f;
            stage_pair(z0, z1, H, L);
            rHg[36 + q] = H;  rLg[36 + q] = L;
            stage_pair(z2, z3, H, L);
            rHg8[36 + q] = H; rLg8[36 + q] = L;
        }
        __syncwarp();

        // ---- x = lrelu(rel @ Wse^T + bse) (1 chunk from pairs 32..39) ----
        float ax[2][4];
        ax[0][0] = smf[OFF_BS + 2 * q];     ax[0][1] = smf[OFF_BS + 2 * q + 1];
        ax[0][2] = ax[0][0];                ax[0][3] = ax[0][1];
        ax[1][0] = smf[OFF_BS + 8 + 2 * q]; ax[1][1] = smf[OFF_BS + 8 + 2 * q + 1];
        ax[1][2] = ax[1][0];                ax[1][3] = ax[1][1];
        {
            unsigned rh[4] = { rHg[32 + q], rHg8[32 + q], rHg[36 + q], rHg8[36 + q] };
            unsigned rl[4] = { rLg[32 + q], rLg8[32 + q], rLg[36 + q], rLg8[36 + q] };
            #pragma unroll
            for (int nt = 0; nt < 2; nt++) {
                int fi = nt * 32 + l;
                uint2 BH = sBH[fi], BL = sBL[fi];
                mmab(ax[nt], rh, BH.x, BH.y);
                mmab(ax[nt], rl, BH.x, BH.y);
                mmab(ax[nt], rh, BL.x, BL.y);
            }
        }
        #pragma unroll
        for (int nt = 0; nt < 2; nt++)
            #pragma unroll
            for (int j = 0; j < 4; j++)
                ax[nt][j] = ax[nt][j] > 0.f ? ax[nt][j] : 0.01f * ax[nt][j];
        {
            unsigned H, L;
            stage_pair(ax[0][0], ax[0][1], H, L); rHg[32 + q] = H;  rLg[32 + q] = L;
            stage_pair(ax[0][2], ax[0][3], H, L); rHg8[32 + q] = H; rLg8[32 + q] = L;
            stage_pair(ax[1][0], ax[1][1], H, L); rHg[36 + q] = H;  rLg[36 + q] = L;
            stage_pair(ax[1][2], ax[1][3], H, L); rHg8[36 + q] = H; rLg8[36 + q] = L;
        }
    }
    __syncwarp();

    // ---- confidence head: softmax(h @ Wconf^T + bconf) ----
    float ac[4];
    ac[0] = smf[OFF_BC + 2 * q]; ac[1] = smf[OFF_BC + 2 * q + 1];
    ac[2] = ac[0];               ac[3] = ac[1];
    #pragma unroll
    for (int ch = 0; ch < 4; ch++) {
        int b0 = ch * 8 + q;
        unsigned rh[4] = { rHg[b0], rHg8[b0], rHg[b0 + 4], rHg8[b0 + 4] };
        unsigned rl[4] = { rLg[b0], rLg8[b0], rLg[b0 + 4], rLg8[b0 + 4] };
        int fi = ch * 32 + l;
        uint2 BH = cBH[fi], BL = cBL[fi];
        mmab(ac, rh, BH.x, BH.y);
        mmab(ac, rl, BH.x, BH.y);
        mmab(ac, rh, BL.x, BL.y);
    }
    {
        bool v0 = (2 * q) < 6, v1 = (2 * q + 1) < 6;
        float la = fmaxf(v0 ? ac[0] : -1e30f, v1 ? ac[1] : -1e30f);
        float lb = fmaxf(v0 ? ac[2] : -1e30f, v1 ? ac[3] : -1e30f);
        la = fmaxf(la, __shfl_xor_sync(0xffffffffu, la, 1));
        la = fmaxf(la, __shfl_xor_sync(0xffffffffu, la, 2));
        lb = fmaxf(lb, __shfl_xor_sync(0xffffffffu, lb, 1));
        lb = fmaxf(lb, __shfl_xor_sync(0xffffffffu, lb, 2));
        float ea0 = v0 ? __expf(ac[0] - la) : 0.f, ea1 = v1 ? __expf(ac[1] - la) : 0.f;
        float eb0 = v0 ? __expf(ac[2] - lb) : 0.f, eb1 = v1 ? __expf(ac[3] - lb) : 0.f;
        float sa = ea0 + ea1, sb = eb0 + eb1;
        sa += __shfl_xor_sync(0xffffffffu, sa, 1); sa += __shfl_xor_sync(0xffffffffu, sa, 2);
        sb += __shfl_xor_sync(0xffffffffu, sb, 1); sb += __shfl_xor_sync(0xffffffffu, sb, 2);
        float ra = frcp_(sa), rb = frcp_(sb);
        if (q < 3) {
            float* cA = out + CONF_BASE + (size_t)(ag0 + g) * NM + 2 * q;
            float* cB = out + CONF_BASE + (size_t)(ag0 + g + 8) * NM + 2 * q;
            *(float2*)cA = make_float2(ea0 * ra, ea1 * ra);
            *(float2*)cB = make_float2(eb0 * rb, eb1 * rb);
        }
    }
}

extern "C" void kernel_launch(void* const* d_in, const int* in_sizes, int n_in,
                              void* d_out, int out_size)
{
    // 0 traj_abs (unused), 1 traj_rel, 2 h0, 3 c0, 4 W_ih, 5 W_hh,
    // 6 b_ih, 7 b_hh, 8 W_se, 9 b_se, 10 W_pos, 11 b_pos, 12 W_conf, 13 b_conf
    const float* traj_rel = (const float*)d_in[1];
    const float* h0       = (const float*)d_in[2];
    const float* c0       = (const float*)d_in[3];
    const float* W_ih     = (const float*)d_in[4];
    const float* W_hh     = (const float*)d_in[5];
    const float* b_ih     = (const float*)d_in[6];
    const float* b_hh     = (const float*)d_in[7];
    const float* W_se     = (const float*)d_in[8];
    const float* b_se     = (const float*)d_in[9];
    const float* W_pos    = (const float*)d_in[10];
    const float* b_pos    = (const float*)d_in[11];
    const float* W_conf   = (const float*)d_in[12];
    const float* b_conf   = (const float*)d_in[13];
    float* out = (float*)d_out;

    (void)cudaFuncSetAttribute(decoder_lstm_kernel,
                               cudaFuncAttributeMaxDynamicSharedMemorySize,
                               SMEM_BYTES);

    decoder_lstm_kernel<<<NBLK, TPB, SMEM_BYTES>>>(
        traj_rel, h0, c0, W_ih, W_hh, b_ih, b_hh,
        W_se, b_se, W_pos, b_pos, W_conf, b_conf, out);
}